// round 17
// baseline (speedup 1.0000x reference)
#include <cuda_runtime.h>
#include <stdint.h>

// Inputs (metadata order):
//   d_in[0] disp        float32 [E,3]   (E = 3,200,000)
//   d_in[1] a           float32 [E]
//   d_in[2] b           float32 [E]
//   d_in[3] edge_index  int32   [2,E]   row0 = src, row1 = dst
//   d_in[4] atom_node   int32   [N]     (N = 100,000)
// Output: float32 [N,3]
//
// force_edge = 2*(b*exp(-r2) - a) * disp ;  out = scatter(+,src) - scatter(+,dst)
//
// Pipeline with PDL + early programmatic-completion triggers:
//   zero_accum --trigger/PDL--> scatter --trigger/PDL--> gather
// Each primary fires cudaTriggerProgrammaticLaunchCompletion() right after its
// fenced final memory op, releasing the dependent kernel before teardown.
// Scatter stays 2 x RED.128/edge (measured at the REDG spread-address floor).

#define N_MAX 100352  // >= 100000

__device__ float4 g_accum[N_MAX];

__global__ __launch_bounds__(256)
void zero_accum_kernel(int n) {
    int i = blockIdx.x * blockDim.x + threadIdx.x;
    if (i < n) g_accum[i] = make_float4(0.f, 0.f, 0.f, 0.f);
    __threadfence();                              // stores visible @ gpu scope
    cudaTriggerProgrammaticLaunchCompletion();    // release scatter early
}

__global__ __launch_bounds__(256)
void edge_force_scatter_kernel(const float* __restrict__ disp,
                               const float* __restrict__ a,
                               const float* __restrict__ b,
                               const int* __restrict__ src,
                               const int* __restrict__ dst,
                               int num_edges) {
    int e = blockIdx.x * blockDim.x + threadIdx.x;
    if (e < num_edges) {
        // Prologue: independent of g_accum -> overlaps the zero kernel.
        float dx = disp[3 * e + 0];
        float dy = disp[3 * e + 1];
        float dz = disp[3 * e + 2];
        float ae = a[e];
        float be = b[e];
        int si = src[e];
        int di = dst[e];

        float r2 = fmaf(dx, dx, fmaf(dy, dy, dz * dz));
        float s = 2.0f * fmaf(be, __expf(-r2), -ae);  // 2*(b*exp(-r2) - a)
        float fx = s * dx, fy = s * dy, fz = s * dz;

        // Wait until the zero kernel's stores are visible.
        cudaGridDependencySynchronize();

        atomicAdd(&g_accum[si], make_float4( fx,  fy,  fz, 0.f));
        atomicAdd(&g_accum[di], make_float4(-fx, -fy, -fz, 0.f));
    } else {
        cudaGridDependencySynchronize();
    }
    __threadfence();                              // order REDs @ gpu scope
    cudaTriggerProgrammaticLaunchCompletion();    // release gather early
}

// One thread per output float: out[idx] = accum[idx/3].{x,y,z}[idx%3].
__global__ __launch_bounds__(256)
void gather_out_kernel(float* __restrict__ out, int n3) {
    int idx = blockIdx.x * blockDim.x + threadIdx.x;
    int i = idx / 3;           // atom row
    int c = idx - 3 * i;       // component 0..2
    const float* acc = (const float*)g_accum;

    // Wait for the scatter's fenced REDs to be visible.
    cudaGridDependencySynchronize();

    if (idx < n3) out[idx] = __ldcg(acc + 4 * i + c);
}

static void launch_pdl(void* func, dim3 grid, dim3 block,
                       void** args, cudaStream_t stream) {
    cudaLaunchConfig_t cfg = {};
    cfg.gridDim = grid;
    cfg.blockDim = block;
    cfg.dynamicSmemBytes = 0;
    cfg.stream = stream;
    cudaLaunchAttribute attr[1];
    attr[0].id = cudaLaunchAttributeProgrammaticStreamSerialization;
    attr[0].val.programmaticStreamSerializationAllowed = 1;
    cfg.attrs = attr;
    cfg.numAttrs = 1;
    cudaLaunchKernelExC(&cfg, func, args);
}

extern "C" void kernel_launch(void* const* d_in, const int* in_sizes, int n_in,
                              void* d_out, int out_size) {
    const float* disp = (const float*)d_in[0];
    const float* a    = (const float*)d_in[1];
    const float* b    = (const float*)d_in[2];
    const int*   ei   = (const int*)d_in[3];   // int32 [2, E]

    int num_edges = in_sizes[1];               // a is [E]
    const int* src = ei;
    const int* dst = ei + num_edges;

    float* out = (float*)d_out;
    int n_atoms = out_size / 3;
    cudaStream_t stream = 0;  // legacy default stream (harness captures it)

    // 1) Zero accumulator (plain launch; fires early-completion trigger).
    {
        int threads = 256;
        int blocks = (n_atoms + threads - 1) / threads;
        zero_accum_kernel<<<blocks, threads>>>(n_atoms);
    }

    // 2) Scatter with PDL: prologue overlaps zeroing; triggers gather early.
    {
        int threads = 256;
        int blocks = (num_edges + threads - 1) / threads;
        void* args[] = {(void*)&disp, (void*)&a, (void*)&b,
                        (void*)&src, (void*)&dst, (void*)&num_edges};
        launch_pdl((void*)edge_force_scatter_kernel,
                   dim3(blocks), dim3(threads), args, stream);
    }

    // 3) Gather with PDL: releases as soon as the scatter's REDs are fenced.
    {
        int threads = 256;
        int n3 = out_size;  // 3 * n_atoms
        int blocks = (n3 + threads - 1) / threads;
        void* args[] = {(void*)&out, (void*)&n3};
        launch_pdl((void*)gather_out_kernel,
                   dim3(blocks), dim3(threads), args, stream);
    }
}